// round 15
// baseline (speedup 1.0000x reference)
#include <cuda_runtime.h>
#include <cuda_bf16.h>
#include <math.h>
#include <cstdint>

#define D     256
#define NMAX  8192
#define BM    128
#define BN    128
#define NB    (NMAX / BM)     // 64 m-blocks per matrix
#define NT    (NMAX / BN)     // 64 j-tiles per m-block
#define TOTAL_TILES (2 * NB * NT)   // 8192
#define GRID_GEMM 148
#define INVT  20.0f            // 1 / 0.05
#define C2E   28.853900817779268f   // INVT * log2(e): exp(INVT*x) = exp2(C2E*x)
#define PITCH 512              // smem row pitch (swizzled, conflict-free)
#define TILE_BYTES (BM * PITCH)        // 65536
#define SMEM_TOTAL (3 * TILE_BYTES)    // 196608 (3-stage B pipeline)

// ---------------------------------------------------------------------------
// Scratch (__device__ globals: allocation-free rule)
// ---------------------------------------------------------------------------
__device__ float g_spos[NMAX];
__device__ float g_rs1[NMAX];
__device__ float g_rs2[NMAX];
__device__ unsigned int g_arrive;   // monotonic grid-barrier ticket (replay-safe)
__device__ __align__(16) __nv_bfloat16 g_Ebf[NMAX * D];
__device__ __align__(16) __nv_bfloat16 g_Pbf[NMAX * D];
__device__ __align__(16) __nv_bfloat16 g_Nbf[NMAX * D];

__device__ __forceinline__ uint32_t smem_to_u32(const void* p) {
    uint32_t a;
    asm("{ .reg .u64 t; cvta.to.shared.u64 t, %1; cvt.u32.u64 %0, t; }" : "=r"(a) : "l"(p));
    return a;
}

// swizzled byte offset for (row, 16B-chunk c16), c16 in 0..31
__device__ __forceinline__ uint32_t off16(uint32_t r, uint32_t c16) {
    return r * PITCH + ((((c16 & 7u) ^ (r & 7u)) | (c16 & 24u)) << 4);
}

__device__ __forceinline__ void mma16816(float* d, const uint32_t* a, uint32_t b0, uint32_t b1) {
    asm volatile(
        "mma.sync.aligned.m16n8k16.row.col.f32.bf16.bf16.f32 "
        "{%0,%1,%2,%3}, {%4,%5,%6,%7}, {%8,%9}, {%0,%1,%2,%3};"
        : "+f"(d[0]), "+f"(d[1]), "+f"(d[2]), "+f"(d[3])
        : "r"(a[0]), "r"(a[1]), "r"(a[2]), "r"(a[3]), "r"(b0), "r"(b1));
}

#define LDSM_X4(r, addr) \
    asm volatile("ldmatrix.sync.aligned.m8n8.x4.shared.b16 {%0,%1,%2,%3}, [%4];" \
        : "=r"((r)[0]), "=r"((r)[1]), "=r"((r)[2]), "=r"((r)[3]) : "r"(addr))

// issue one 128x256 bf16 tile (gmem row pitch 512B) into swizzled smem via cp.async
__device__ __forceinline__ void issue_tile(uint32_t sdst, const __nv_bfloat16* src, int tid) {
    #pragma unroll
    for (int i = 0; i < 16; i++) {
        int flat = tid + (i << 8);
        uint32_t r = (uint32_t)flat >> 5, c = (uint32_t)flat & 31;
        uint32_t d = sdst + off16(r, c);
        const char* g = (const char*)src + r * 512 + c * 16;
        asm volatile("cp.async.cg.shared.global [%0], [%1], 16;" :: "r"(d), "l"(g));
    }
}

// ---------------------------------------------------------------------------
// normalize one row (warp-collective, two-phase): bf16 outputs + spos + rs zero
// ---------------------------------------------------------------------------
__device__ __forceinline__ void normalize_row(int row, int lane,
                                              const float* __restrict__ e,
                                              const float* __restrict__ p,
                                              const float* __restrict__ nn) {
    size_t base = (size_t)row * D + lane * 8;
    if (lane == 0) { g_rs1[row] = 0.f; g_rs2[row] = 0.f; }

    // phase 1: e and p (dot needed)
    {
        float ve[8], vp[8];
        *(float4*)&ve[0] = *(const float4*)(e + base);
        *(float4*)&ve[4] = *(const float4*)(e + base + 4);
        *(float4*)&vp[0] = *(const float4*)(p + base);
        *(float4*)&vp[4] = *(const float4*)(p + base + 4);

        float se = 0.f, sp = 0.f;
        #pragma unroll
        for (int i = 0; i < 8; i++) { se += ve[i]*ve[i]; sp += vp[i]*vp[i]; }
        #pragma unroll
        for (int o = 16; o > 0; o >>= 1) {
            se += __shfl_xor_sync(0xffffffffu, se, o);
            sp += __shfl_xor_sync(0xffffffffu, sp, o);
        }
        float ie = 1.f / fmaxf(sqrtf(se), 1e-8f);
        float ip = 1.f / fmaxf(sqrtf(sp), 1e-8f);

        float d = 0.f;
        __nv_bfloat162 be[4], bp[4];
        #pragma unroll
        for (int i = 0; i < 4; i++) {
            float e0 = ve[2*i]*ie, e1 = ve[2*i+1]*ie;
            float p0 = vp[2*i]*ip, p1 = vp[2*i+1]*ip;
            d += e0*p0 + e1*p1;
            be[i] = __float22bfloat162_rn(make_float2(e0, e1));
            bp[i] = __float22bfloat162_rn(make_float2(p0, p1));
        }
        *(uint4*)(g_Ebf + base) = *(uint4*)be;
        *(uint4*)(g_Pbf + base) = *(uint4*)bp;
        #pragma unroll
        for (int o = 16; o > 0; o >>= 1) d += __shfl_xor_sync(0xffffffffu, d, o);
        if (lane == 0) g_spos[row] = d;
    }
    // phase 2: n alone
    {
        float vn[8];
        *(float4*)&vn[0] = *(const float4*)(nn + base);
        *(float4*)&vn[4] = *(const float4*)(nn + base + 4);
        float sn = 0.f;
        #pragma unroll
        for (int i = 0; i < 8; i++) sn += vn[i]*vn[i];
        #pragma unroll
        for (int o = 16; o > 0; o >>= 1) sn += __shfl_xor_sync(0xffffffffu, sn, o);
        float iv = 1.f / fmaxf(sqrtf(sn), 1e-8f);
        __nv_bfloat162 bn[4];
        #pragma unroll
        for (int i = 0; i < 4; i++)
            bn[i] = __float22bfloat162_rn(make_float2(vn[2*i]*iv, vn[2*i+1]*iv));
        *(uint4*)(g_Nbf + base) = *(uint4*)bn;
    }
}

// ---------------------------------------------------------------------------
// Kernel: persistent [normalize -> grid barrier -> HMMA GEMM + exp row-sum].
// 148 CTAs, 1/SM, all co-resident -> spin grid-barrier is deadlock-free.
// Ticket is monotonic (target = (old/148+1)*148) so graph replays need no reset.
// GEMM mainloop is the frozen R12 configuration (session best).
// ---------------------------------------------------------------------------
__global__ void __launch_bounds__(256, 1) fused_gemm(const float* __restrict__ e,
                                                     const float* __restrict__ p,
                                                     const float* __restrict__ nn,
                                                     float* __restrict__ out) {
    extern __shared__ char smem[];
    const uint32_t sbase = smem_to_u32(smem);
    const int tid  = threadIdx.x;
    const int wid  = tid >> 5, lane = tid & 31;

    // ================= phase 0: normalize (1184 warps over 8192 rows) ======
    if (blockIdx.x == 0 && tid == 0) out[0] = 0.f;
    {
        int gwarp = blockIdx.x * 8 + wid;
        for (int row = gwarp; row < NMAX; row += GRID_GEMM * 8)
            normalize_row(row, lane, e, p, nn);
    }
    __syncthreads();
    // grid barrier (replay-safe monotonic ticket)
    if (tid == 0) {
        __threadfence();
        unsigned int old = atomicAdd(&g_arrive, 1u);
        unsigned int target = (old / GRID_GEMM + 1u) * GRID_GEMM;
        unsigned int v;
        do {
            asm volatile("ld.acquire.gpu.u32 %0, [%1];" : "=r"(v) : "l"(&g_arrive));
        } while (v < target);
    }
    __syncthreads();

    // ================= phase 1: GEMM (frozen R12 mainloop) =================
    const int warpM = (wid & 3) * 32;
    const int warpN = (wid >> 2) * 64;

    const uint32_t arow = (lane & 7) + ((lane >> 3) & 1) * 8;
    const uint32_t khi  = (uint32_t)(lane >> 4);
    const uint32_t brow = (lane & 7) + (lane >> 4) * 8;
    const uint32_t bhi  = (uint32_t)((lane >> 3) & 1);

    int t   = (int)(((long long)blockIdx.x * TOTAL_TILES) / GRID_GEMM);
    int end = (int)(((long long)(blockIdx.x + 1) * TOTAL_TILES) / GRID_GEMM);

    while (t < end) {
        const int ab  = t >> 6;
        const int j0  = t & 63;
        const int seg = min(NT - j0, end - t);
        const int j1  = j0 + seg;
        const int mat = ab >> 6;
        const int bm  = ab & (NB - 1);
        const __nv_bfloat16* A = mat ? g_Pbf : g_Ebf;
        const __nv_bfloat16* B = mat ? g_Ebf : g_Nbf;
        float* rs = mat ? g_rs2 : g_rs1;
        const int row0 = bm * BM;

        // ---- stage A tile into buf0 (swizzled), read frags into registers
        {
            const uint4* g = (const uint4*)(A + (size_t)row0 * D);
            #pragma unroll
            for (int i = 0; i < 16; i++) {
                int flat = tid + (i << 8);
                uint32_t r = (uint32_t)flat >> 5, c = (uint32_t)flat & 31;
                *(uint4*)(smem + off16(r, c)) = g[r * 32 + c];
            }
        }
        __syncthreads();

        uint32_t aF[2][16][4];
        #pragma unroll
        for (int mt = 0; mt < 2; mt++) {
            uint32_t row = (uint32_t)(warpM + mt * 16) + arow;
            #pragma unroll
            for (int k = 0; k < 16; k++)
                LDSM_X4(aF[mt][k], sbase + off16(row, 2u * k + khi));
        }
        __syncthreads();

        // ---- prologue: 2 B tiles in flight
        issue_tile(sbase, B + (size_t)j0 * BN * D, tid);
        asm volatile("cp.async.commit_group;");
        if (j0 + 1 < j1) {
            issue_tile(sbase + TILE_BYTES, B + (size_t)(j0 + 1) * BN * D, tid);
            asm volatile("cp.async.commit_group;");
        }

        float rowAcc[4] = {0.f, 0.f, 0.f, 0.f};

        for (int j = j0; j < j1; j++) {
            const int sj = j - j0;
            if (j + 1 < j1) asm volatile("cp.async.wait_group 1;" ::: "memory");
            else            asm volatile("cp.async.wait_group 0;" ::: "memory");
            __syncthreads();   // buffer (sj)%3 data visible
            if (j + 2 < j1) {
                issue_tile(sbase + (uint32_t)((sj + 2) % 3) * TILE_BYTES,
                           B + (size_t)(j + 2) * BN * D, tid);
                asm volatile("cp.async.commit_group;");
            }
            const uint32_t cbase = sbase + (uint32_t)(sj % 3) * TILE_BYTES;

            #pragma unroll
            for (int half = 0; half < 2; half++) {
                float acc[2][4][4];
                #pragma unroll
                for (int mt = 0; mt < 2; mt++)
                    #pragma unroll
                    for (int nt = 0; nt < 4; nt++)
                        #pragma unroll
                        for (int c = 0; c < 4; c++) acc[mt][nt][c] = 0.f;

                const uint32_t rowp0 = (uint32_t)(warpN + (half * 2 + 0) * 16) + brow;
                const uint32_t rowp1 = (uint32_t)(warpN + (half * 2 + 1) * 16) + brow;

                uint32_t bf[2][8];
                LDSM_X4(&bf[0][0], cbase + off16(rowp0, bhi));
                LDSM_X4(&bf[0][4], cbase + off16(rowp1, bhi));
                #pragma unroll
                for (int k = 0; k < 16; k++) {
                    const int c = k & 1, n = c ^ 1;
                    if (k < 15) {
                        uint32_t c16 = 2u * (k + 1) + bhi;
                        LDSM_X4(&bf[n][0], cbase + off16(rowp0, c16));
                        LDSM_X4(&bf[n][4], cbase + off16(rowp1, c16));
                    }
                    #pragma unroll
                    for (int mt = 0; mt < 2; mt++) {
                        mma16816(acc[mt][0], aF[mt][k], bf[c][0], bf[c][1]);
                        mma16816(acc[mt][1], aF[mt][k], bf[c][2], bf[c][3]);
                        mma16816(acc[mt][2], aF[mt][k], bf[c][4], bf[c][5]);
                        mma16816(acc[mt][3], aF[mt][k], bf[c][6], bf[c][7]);
                    }
                }

                // epilogue for this half overlaps next half's MMAs (MUFU hidden)
                #pragma unroll
                for (int mt = 0; mt < 2; mt++)
                    #pragma unroll
                    for (int nt = 0; nt < 4; nt++) {
                        rowAcc[mt*2+0] += exp2f(C2E * acc[mt][nt][0]) + exp2f(C2E * acc[mt][nt][1]);
                        rowAcc[mt*2+1] += exp2f(C2E * acc[mt][nt][2]) + exp2f(C2E * acc[mt][nt][3]);
                    }
            }

            __syncthreads();   // all warps done with buf sj%3 before it is refilled
        }

        // ---- merge partial row sums (quad lanes share rows)
        #pragma unroll
        for (int i = 0; i < 4; i++) {
            rowAcc[i] += __shfl_xor_sync(0xffffffffu, rowAcc[i], 1);
            rowAcc[i] += __shfl_xor_sync(0xffffffffu, rowAcc[i], 2);
        }
        __syncthreads();
        float* red = (float*)smem;
        if ((lane & 3) == 0) {
            int rbase = warpM + (lane >> 2);
            int wn = wid >> 2;
            red[(rbase +  0) * 2 + wn] = rowAcc[0];
            red[(rbase +  8) * 2 + wn] = rowAcc[1];
            red[(rbase + 16) * 2 + wn] = rowAcc[2];
            red[(rbase + 24) * 2 + wn] = rowAcc[3];
        }
        __syncthreads();
        if (tid < BM) atomicAdd(&rs[row0 + tid], red[tid * 2] + red[tid * 2 + 1]);
        __syncthreads();

        t += seg;
    }
}

// ---------------------------------------------------------------------------
// Kernel 3: parallel loss assembly; block partials merged via atomicAdd.
// ---------------------------------------------------------------------------
__global__ void finalize_kernel(float* __restrict__ out, int N) {
    __shared__ float sh[32];
    int i = blockIdx.x * blockDim.x + threadIdx.x;
    float s = 0.f;
    if (i < N) {
        float sp = g_spos[i] * INVT;
        s = log1pf(__expf(-sp) * g_rs1[i]) + (logf(g_rs2[i]) - sp);
    }
    int lane = threadIdx.x & 31, w = threadIdx.x >> 5;
    #pragma unroll
    for (int o = 16; o > 0; o >>= 1) s += __shfl_xor_sync(0xffffffffu, s, o);
    if (lane == 0) sh[w] = s;
    __syncthreads();
    if (w == 0) {
        float r = (lane < (int)(blockDim.x >> 5)) ? sh[lane] : 0.f;
        #pragma unroll
        for (int o = 16; o > 0; o >>= 1) r += __shfl_xor_sync(0xffffffffu, r, o);
        if (lane == 0) atomicAdd(out, r / (float)N);
    }
}

// ---------------------------------------------------------------------------
extern "C" void kernel_launch(void* const* d_in, const int* in_sizes, int n_in,
                              void* d_out, int out_size) {
    const float* e  = (const float*)d_in[0];
    const float* p  = (const float*)d_in[1];
    const float* nn = (const float*)d_in[2];
    const int N = in_sizes[0] / D;   // 8192

    static bool attr_set = false;
    if (!attr_set) {
        cudaFuncSetAttribute(fused_gemm, cudaFuncAttributeMaxDynamicSharedMemorySize, SMEM_TOTAL);
        attr_set = true;
    }

    fused_gemm<<<GRID_GEMM, 256, SMEM_TOTAL>>>(e, p, nn, (float*)d_out);
    finalize_kernel<<<N / 1024, 1024>>>((float*)d_out, N);
}

// round 16
// speedup vs baseline: 1.0125x; 1.0125x over previous
#include <cuda_runtime.h>
#include <cuda_bf16.h>
#include <math.h>
#include <cstdint>

#define D     256
#define NMAX  8192
#define BM    128
#define BN    128
#define NB    (NMAX / BM)     // 64 m-blocks per matrix
#define NT    (NMAX / BN)     // 64 j-tiles per m-block
#define TOTAL_TILES (2 * NB * NT)   // 8192
#define GRID_GEMM 148
#define INVT  20.0f            // 1 / 0.05
#define C2E   28.853900817779268f   // INVT * log2(e): exp(INVT*x) = exp2(C2E*x)
#define PITCH 512              // smem row pitch (swizzled, conflict-free)
#define TILE_BYTES (BM * PITCH)        // 65536
#define SMEM_TOTAL (3 * TILE_BYTES)    // 196608 (3-stage B pipeline)

// ---------------------------------------------------------------------------
// Scratch (__device__ globals: allocation-free rule)
// ---------------------------------------------------------------------------
__device__ float g_spos[NMAX];
__device__ float g_rs1[NMAX];
__device__ float g_rs2[NMAX];
__device__ __align__(16) __nv_bfloat16 g_Ebf[NMAX * D];
__device__ __align__(16) __nv_bfloat16 g_Pbf[NMAX * D];
__device__ __align__(16) __nv_bfloat16 g_Nbf[NMAX * D];

__device__ __forceinline__ uint32_t smem_to_u32(const void* p) {
    uint32_t a;
    asm("{ .reg .u64 t; cvta.to.shared.u64 t, %1; cvt.u32.u64 %0, t; }" : "=r"(a) : "l"(p));
    return a;
}

// swizzled byte offset for (row, 16B-chunk c16), c16 in 0..31
__device__ __forceinline__ uint32_t off16(uint32_t r, uint32_t c16) {
    return r * PITCH + ((((c16 & 7u) ^ (r & 7u)) | (c16 & 24u)) << 4);
}

__device__ __forceinline__ void mma16816(float* d, const uint32_t* a, uint32_t b0, uint32_t b1) {
    asm volatile(
        "mma.sync.aligned.m16n8k16.row.col.f32.bf16.bf16.f32 "
        "{%0,%1,%2,%3}, {%4,%5,%6,%7}, {%8,%9}, {%0,%1,%2,%3};"
        : "+f"(d[0]), "+f"(d[1]), "+f"(d[2]), "+f"(d[3])
        : "r"(a[0]), "r"(a[1]), "r"(a[2]), "r"(a[3]), "r"(b0), "r"(b1));
}

#define LDSM_X4(r, addr) \
    asm volatile("ldmatrix.sync.aligned.m8n8.x4.shared.b16 {%0,%1,%2,%3}, [%4];" \
        : "=r"((r)[0]), "=r"((r)[1]), "=r"((r)[2]), "=r"((r)[3]) : "r"(addr))

// issue one 128x256 bf16 tile (gmem row pitch 512B) into swizzled smem via cp.async
__device__ __forceinline__ void issue_tile(uint32_t sdst, const __nv_bfloat16* src, int tid) {
    #pragma unroll
    for (int i = 0; i < 16; i++) {
        int flat = tid + (i << 8);
        uint32_t r = (uint32_t)flat >> 5, c = (uint32_t)flat & 31;
        uint32_t d = sdst + off16(r, c);
        const char* g = (const char*)src + r * 512 + c * 16;
        asm volatile("cp.async.cg.shared.global [%0], [%1], 16;" :: "r"(d), "l"(g));
    }
}

// ---------------------------------------------------------------------------
// Kernel 1: normalize, warp-per-row, two phases (e+p, then n).
// Also zeroes rs accumulators and d_out.
// ---------------------------------------------------------------------------
__global__ void normalize_kernel(const float* __restrict__ e,
                                 const float* __restrict__ p,
                                 const float* __restrict__ nn,
                                 float* __restrict__ out) {
    int row  = (blockIdx.x * blockDim.x + threadIdx.x) >> 5;
    int lane = threadIdx.x & 31;
    size_t base = (size_t)row * D + lane * 8;

    if (lane == 0) { g_rs1[row] = 0.f; g_rs2[row] = 0.f; }
    if (blockIdx.x == 0 && threadIdx.x == 0) out[0] = 0.f;

    // ---- phase 1: e and p together (dot needed)
    {
        float ve[8], vp[8];
        *(float4*)&ve[0] = *(const float4*)(e + base);
        *(float4*)&ve[4] = *(const float4*)(e + base + 4);
        *(float4*)&vp[0] = *(const float4*)(p + base);
        *(float4*)&vp[4] = *(const float4*)(p + base + 4);

        float se = 0.f, sp = 0.f;
        #pragma unroll
        for (int i = 0; i < 8; i++) { se += ve[i]*ve[i]; sp += vp[i]*vp[i]; }
        #pragma unroll
        for (int o = 16; o > 0; o >>= 1) {
            se += __shfl_xor_sync(0xffffffffu, se, o);
            sp += __shfl_xor_sync(0xffffffffu, sp, o);
        }
        float ie = 1.f / fmaxf(sqrtf(se), 1e-8f);
        float ip = 1.f / fmaxf(sqrtf(sp), 1e-8f);

        float d = 0.f;
        __nv_bfloat162 be[4], bp[4];
        #pragma unroll
        for (int i = 0; i < 4; i++) {
            float e0 = ve[2*i]*ie, e1 = ve[2*i+1]*ie;
            float p0 = vp[2*i]*ip, p1 = vp[2*i+1]*ip;
            d += e0*p0 + e1*p1;
            be[i] = __float22bfloat162_rn(make_float2(e0, e1));
            bp[i] = __float22bfloat162_rn(make_float2(p0, p1));
        }
        *(uint4*)(g_Ebf + base) = *(uint4*)be;
        *(uint4*)(g_Pbf + base) = *(uint4*)bp;
        #pragma unroll
        for (int o = 16; o > 0; o >>= 1) d += __shfl_xor_sync(0xffffffffu, d, o);
        if (lane == 0) g_spos[row] = d;
    }

    // ---- phase 2: n alone
    {
        float vn[8];
        *(float4*)&vn[0] = *(const float4*)(nn + base);
        *(float4*)&vn[4] = *(const float4*)(nn + base + 4);
        float sn = 0.f;
        #pragma unroll
        for (int i = 0; i < 8; i++) sn += vn[i]*vn[i];
        #pragma unroll
        for (int o = 16; o > 0; o >>= 1) sn += __shfl_xor_sync(0xffffffffu, sn, o);
        float iv = 1.f / fmaxf(sqrtf(sn), 1e-8f);
        __nv_bfloat162 bn[4];
        #pragma unroll
        for (int i = 0; i < 4; i++)
            bn[i] = __float22bfloat162_rn(make_float2(vn[2*i]*iv, vn[2*i+1]*iv));
        *(uint4*)(g_Nbf + base) = *(uint4*)bn;
    }
}

// ---------------------------------------------------------------------------
// Kernel 2: persistent HMMA GEMM + fused exp row-sum (frozen R12 config,
// session best — every structural edit in R7-R11, R14 regressed).
// ---------------------------------------------------------------------------
__global__ void __launch_bounds__(256, 1) gemm_expsum_mma() {
    extern __shared__ char smem[];
    const uint32_t sbase = smem_to_u32(smem);
    const int tid  = threadIdx.x;
    const int wid  = tid >> 5, lane = tid & 31;

    const int warpM = (wid & 3) * 32;
    const int warpN = (wid >> 2) * 64;

    const uint32_t arow = (lane & 7) + ((lane >> 3) & 1) * 8;
    const uint32_t khi  = (uint32_t)(lane >> 4);
    const uint32_t brow = (lane & 7) + (lane >> 4) * 8;
    const uint32_t bhi  = (uint32_t)((lane >> 3) & 1);

    int t   = (int)(((long long)blockIdx.x * TOTAL_TILES) / GRID_GEMM);
    int end = (int)(((long long)(blockIdx.x + 1) * TOTAL_TILES) / GRID_GEMM);

    while (t < end) {
        const int ab  = t >> 6;
        const int j0  = t & 63;
        const int seg = min(NT - j0, end - t);
        const int j1  = j0 + seg;
        const int mat = ab >> 6;
        const int bm  = ab & (NB - 1);
        const __nv_bfloat16* A = mat ? g_Pbf : g_Ebf;
        const __nv_bfloat16* B = mat ? g_Ebf : g_Nbf;
        float* rs = mat ? g_rs2 : g_rs1;
        const int row0 = bm * BM;

        // ---- stage A tile into buf0 (swizzled), read frags into registers
        {
            const uint4* g = (const uint4*)(A + (size_t)row0 * D);
            #pragma unroll
            for (int i = 0; i < 16; i++) {
                int flat = tid + (i << 8);
                uint32_t r = (uint32_t)flat >> 5, c = (uint32_t)flat & 31;
                *(uint4*)(smem + off16(r, c)) = g[r * 32 + c];
            }
        }
        __syncthreads();

        uint32_t aF[2][16][4];
        #pragma unroll
        for (int mt = 0; mt < 2; mt++) {
            uint32_t row = (uint32_t)(warpM + mt * 16) + arow;
            #pragma unroll
            for (int k = 0; k < 16; k++)
                LDSM_X4(aF[mt][k], sbase + off16(row, 2u * k + khi));
        }
        __syncthreads();

        // ---- prologue: 2 B tiles in flight
        issue_tile(sbase, B + (size_t)j0 * BN * D, tid);
        asm volatile("cp.async.commit_group;");
        if (j0 + 1 < j1) {
            issue_tile(sbase + TILE_BYTES, B + (size_t)(j0 + 1) * BN * D, tid);
            asm volatile("cp.async.commit_group;");
        }

        float rowAcc[4] = {0.f, 0.f, 0.f, 0.f};

        for (int j = j0; j < j1; j++) {
            const int sj = j - j0;
            if (j + 1 < j1) asm volatile("cp.async.wait_group 1;" ::: "memory");
            else            asm volatile("cp.async.wait_group 0;" ::: "memory");
            __syncthreads();   // buffer (sj)%3 data visible
            if (j + 2 < j1) {
                issue_tile(sbase + (uint32_t)((sj + 2) % 3) * TILE_BYTES,
                           B + (size_t)(j + 2) * BN * D, tid);
                asm volatile("cp.async.commit_group;");
            }
            const uint32_t cbase = sbase + (uint32_t)(sj % 3) * TILE_BYTES;

            #pragma unroll
            for (int half = 0; half < 2; half++) {
                float acc[2][4][4];
                #pragma unroll
                for (int mt = 0; mt < 2; mt++)
                    #pragma unroll
                    for (int nt = 0; nt < 4; nt++)
                        #pragma unroll
                        for (int c = 0; c < 4; c++) acc[mt][nt][c] = 0.f;

                const uint32_t rowp0 = (uint32_t)(warpN + (half * 2 + 0) * 16) + brow;
                const uint32_t rowp1 = (uint32_t)(warpN + (half * 2 + 1) * 16) + brow;

                uint32_t bf[2][8];
                LDSM_X4(&bf[0][0], cbase + off16(rowp0, bhi));
                LDSM_X4(&bf[0][4], cbase + off16(rowp1, bhi));
                #pragma unroll
                for (int k = 0; k < 16; k++) {
                    const int c = k & 1, n = c ^ 1;
                    if (k < 15) {
                        uint32_t c16 = 2u * (k + 1) + bhi;
                        LDSM_X4(&bf[n][0], cbase + off16(rowp0, c16));
                        LDSM_X4(&bf[n][4], cbase + off16(rowp1, c16));
                    }
                    #pragma unroll
                    for (int mt = 0; mt < 2; mt++) {
                        mma16816(acc[mt][0], aF[mt][k], bf[c][0], bf[c][1]);
                        mma16816(acc[mt][1], aF[mt][k], bf[c][2], bf[c][3]);
                        mma16816(acc[mt][2], aF[mt][k], bf[c][4], bf[c][5]);
                        mma16816(acc[mt][3], aF[mt][k], bf[c][6], bf[c][7]);
                    }
                }

                // epilogue for this half overlaps next half's MMAs (MUFU hidden)
                #pragma unroll
                for (int mt = 0; mt < 2; mt++)
                    #pragma unroll
                    for (int nt = 0; nt < 4; nt++) {
                        rowAcc[mt*2+0] += exp2f(C2E * acc[mt][nt][0]) + exp2f(C2E * acc[mt][nt][1]);
                        rowAcc[mt*2+1] += exp2f(C2E * acc[mt][nt][2]) + exp2f(C2E * acc[mt][nt][3]);
                    }
            }

            __syncthreads();   // all warps done with buf sj%3 before it is refilled
        }

        // ---- merge partial row sums (quad lanes share rows)
        #pragma unroll
        for (int i = 0; i < 4; i++) {
            rowAcc[i] += __shfl_xor_sync(0xffffffffu, rowAcc[i], 1);
            rowAcc[i] += __shfl_xor_sync(0xffffffffu, rowAcc[i], 2);
        }
        __syncthreads();
        float* red = (float*)smem;
        if ((lane & 3) == 0) {
            int rbase = warpM + (lane >> 2);
            int wn = wid >> 2;
            red[(rbase +  0) * 2 + wn] = rowAcc[0];
            red[(rbase +  8) * 2 + wn] = rowAcc[1];
            red[(rbase + 16) * 2 + wn] = rowAcc[2];
            red[(rbase + 24) * 2 + wn] = rowAcc[3];
        }
        __syncthreads();
        if (tid < BM) atomicAdd(&rs[row0 + tid], red[tid * 2] + red[tid * 2 + 1]);
        __syncthreads();

        t += seg;
    }
}

// ---------------------------------------------------------------------------
// Kernel 3: loss assembly, 1 row per thread, 32 CTAs; atomicAdd merge.
// ---------------------------------------------------------------------------
__global__ void finalize_kernel(float* __restrict__ out, int N) {
    __shared__ float sh[8];
    int i = blockIdx.x * blockDim.x + threadIdx.x;
    float s = 0.f;
    if (i < N) {
        float sp = g_spos[i] * INVT;
        s = log1pf(__expf(-sp) * g_rs1[i]) + (logf(g_rs2[i]) - sp);
    }
    int lane = threadIdx.x & 31, w = threadIdx.x >> 5;
    #pragma unroll
    for (int o = 16; o > 0; o >>= 1) s += __shfl_xor_sync(0xffffffffu, s, o);
    if (lane == 0) sh[w] = s;
    __syncthreads();
    if (w == 0) {
        float r = (lane < 8) ? sh[lane] : 0.f;
        #pragma unroll
        for (int o = 4; o > 0; o >>= 1) r += __shfl_xor_sync(0xffffffffu, r, o);
        if (lane == 0) atomicAdd(out, r / (float)N);
    }
}

// ---------------------------------------------------------------------------
extern "C" void kernel_launch(void* const* d_in, const int* in_sizes, int n_in,
                              void* d_out, int out_size) {
    const float* e  = (const float*)d_in[0];
    const float* p  = (const float*)d_in[1];
    const float* nn = (const float*)d_in[2];
    const int N = in_sizes[0] / D;   // 8192

    static bool attr_set = false;
    if (!attr_set) {
        cudaFuncSetAttribute(gemm_expsum_mma, cudaFuncAttributeMaxDynamicSharedMemorySize, SMEM_TOTAL);
        attr_set = true;
    }

    normalize_kernel<<<N / 8, 256>>>(e, p, nn, (float*)d_out);
    gemm_expsum_mma<<<GRID_GEMM, 256, SMEM_TOTAL>>>();
    finalize_kernel<<<N / 256, 256>>>((float*)d_out, N);
}